// round 13
// baseline (speedup 1.0000x reference)
#include <cuda_runtime.h>
#include <math.h>

// R12 with ONLY k1 parallelism pushed: SPLITS 512 -> 1024 (4096 CTAs).
//   k1: split-K matvec, SPLITS=1024, 4 rows/CTA, 12 indep loads/thread
//   k2: fused reduction 1024->1 + input + tanh -> yout (32 CTAs x 1024 thr)
//   k3: flat hebb update, 16384 CTAs, 1 float4/thread (unchanged, 19.0us)

#define N 4096
#define SPLITS 1024            // row splits (split-K)
#define ROWS_PER (N / SPLITS)  // 4 rows per split
#define MV_THREADS 256
#define COL_BLOCKS (N / (MV_THREADS * 4))  // 4

// Deterministic split-K scratch (16 MB). No atomics -> bit-identical replays.
__device__ float g_partial[SPLITS * N];

// ---------------------------------------------------------------------------
// Kernel 1: partial matvec, 4096 CTAs, 4 fully-unrolled rows.
// ---------------------------------------------------------------------------
__global__ void __launch_bounds__(MV_THREADS) k_matvec_partial(
    const float* __restrict__ yin,
    const float* __restrict__ w,
    const float* __restrict__ alpha,
    const float* __restrict__ hebb)
{
    const int j  = blockIdx.x * (MV_THREADS * 4) + threadIdx.x * 4;
    const int r0 = blockIdx.y * ROWS_PER;

    const float4* __restrict__ wp = reinterpret_cast<const float4*>(w     + (size_t)r0 * N + j);
    const float4* __restrict__ ap = reinterpret_cast<const float4*>(alpha + (size_t)r0 * N + j);
    const float4* __restrict__ hp = reinterpret_cast<const float4*>(hebb  + (size_t)r0 * N + j);
    const int stride4 = N / 4;

    float4 acc = make_float4(0.f, 0.f, 0.f, 0.f);

    #pragma unroll
    for (int i = 0; i < ROWS_PER; ++i) {
        const float  y  = __ldg(&yin[r0 + i]);
        const float4 w4 = __ldcs(wp + (size_t)i * stride4);
        const float4 a4 = __ldcs(ap + (size_t)i * stride4);
        const float4 h4 = __ldg (hp + (size_t)i * stride4);
        acc.x = fmaf(y, fmaf(a4.x, h4.x, w4.x), acc.x);
        acc.y = fmaf(y, fmaf(a4.y, h4.y, w4.y), acc.y);
        acc.z = fmaf(y, fmaf(a4.z, h4.z, w4.z), acc.z);
        acc.w = fmaf(y, fmaf(a4.w, h4.w, w4.w), acc.w);
    }

    *reinterpret_cast<float4*>(&g_partial[(size_t)blockIdx.y * N + j]) = acc;
}

// ---------------------------------------------------------------------------
// Kernel 2 (fused): 1024-way column reduction + input + tanh -> yout.
// 32 CTAs x 1024 threads; thread (sg, col) sums 128 partials, coalesced,
// mostly L2-resident; smem reduce 8 -> 1.
// ---------------------------------------------------------------------------
#define R_THREADS 1024
#define R_GROUPS  8
#define R_COLS    128                    // columns per CTA
#define R_PER_T   (SPLITS / R_GROUPS)    // 128 partials per thread

__global__ void __launch_bounds__(R_THREADS) k_reduce_fused(
    const float* __restrict__ input,
    float* __restrict__ out_yout)
{
    __shared__ float red[R_GROUPS][R_COLS];

    const int tid = threadIdx.x;
    const int col = tid & (R_COLS - 1);          // 0..127
    const int sg  = tid >> 7;                    // 0..7
    const int j   = blockIdx.x * R_COLS + col;   // global column

    const float* __restrict__ gp = g_partial + (size_t)sg * R_PER_T * N + j;

    float s = 0.f;
    #pragma unroll 16
    for (int p = 0; p < R_PER_T; ++p)
        s += gp[(size_t)p * N];

    red[sg][col] = s;
    __syncthreads();

    if (sg == 0) {
        float t = red[0][col];
        #pragma unroll
        for (int g = 1; g < R_GROUPS; ++g)
            t += red[g][col];
        out_yout[j] = tanhf(t + __ldg(&input[j]));
    }
}

// ---------------------------------------------------------------------------
// Kernel 3: flat hebb update (unchanged — measured 19.0us).
// ---------------------------------------------------------------------------
__global__ void __launch_bounds__(256) k_hebb_update(
    const float* __restrict__ hebb,
    const float* __restrict__ yin,
    const float* __restrict__ yout,   // = d_out
    const float* __restrict__ eta,
    float* __restrict__ out_hebb)     // = d_out + N
{
    const size_t t   = (size_t)blockIdx.x * blockDim.x + threadIdx.x;
    const size_t idx = t * 4;                 // element index in N*N
    const int i = (int)(idx >> 12);           // row (N = 2^12)
    const int j = (int)(idx & (N - 1));       // col

    const float e   = eta[0];
    const float ome = 1.f - e;
    const float yie = yin[i] * e;             // warp-uniform broadcast

    const float4 h  = __ldg(reinterpret_cast<const float4*>(hebb + idx));
    const float4 yo = __ldg(reinterpret_cast<const float4*>(yout + j));

    float4 r;
    r.x = fmaf(ome, h.x, yie * yo.x);
    r.y = fmaf(ome, h.y, yie * yo.y);
    r.z = fmaf(ome, h.z, yie * yo.z);
    r.w = fmaf(ome, h.w, yie * yo.w);

    __stcs(reinterpret_cast<float4*>(out_hebb + idx), r);
}

extern "C" void kernel_launch(void* const* d_in, const int* in_sizes, int n_in,
                              void* d_out, int out_size)
{
    const float* input = (const float*)d_in[0];
    const float* yin   = (const float*)d_in[1];
    const float* hebb  = (const float*)d_in[2];
    const float* w     = (const float*)d_in[3];
    const float* alpha = (const float*)d_in[4];
    const float* eta   = (const float*)d_in[5];

    float* out      = (float*)d_out;
    float* out_yout = out;
    float* out_hebb = out + N;

    dim3 g1(COL_BLOCKS, SPLITS);   // 4 x 1024 = 4096 CTAs
    k_matvec_partial<<<g1, MV_THREADS>>>(yin, w, alpha, hebb);

    k_reduce_fused<<<N / R_COLS, R_THREADS>>>(input, out_yout);   // 32 CTAs

    const int hb_blocks = (N * N) / (4 * 256);   // 16384
    k_hebb_update<<<hb_blocks, 256>>>(hebb, yin, out_yout, eta, out_hebb);
}

// round 14
// speedup vs baseline: 1.0331x; 1.0331x over previous
#include <cuda_runtime.h>
#include <math.h>

// Composition of measured-best pieces:
//   k1 : split-K matvec, SPLITS=1024 (measured 32.1us @ 80.9% DRAM in R13)
//   k2a: reduce 1024 -> 32 partials/column, 512 CTAs (fixes R13's 32-CTA choke)
//   k2b: 32-way sum + input + tanh -> yout
//   k3 : flat hebb update, 16384 CTAs, 1 float4/thread (measured 19.0us)

#define N 4096
#define SPLITS 1024            // row splits (split-K)
#define ROWS_PER (N / SPLITS)  // 4 rows per split
#define MV_THREADS 256
#define COL_BLOCKS (N / (MV_THREADS * 4))  // 4

#define CHUNKS 32                      // stage-2 fan-in
#define P_PER_CHUNK (SPLITS / CHUNKS)  // 32 partials per chunk

// Deterministic split-K scratch. No atomics -> bit-identical replays.
__device__ float g_partial[SPLITS * N];   // 16 MB
__device__ float g_partial2[CHUNKS * N];  // 512 KB

// ---------------------------------------------------------------------------
// Kernel 1: partial matvec, 4096 CTAs, 4 fully-unrolled rows. (R13-identical)
// ---------------------------------------------------------------------------
__global__ void __launch_bounds__(MV_THREADS) k_matvec_partial(
    const float* __restrict__ yin,
    const float* __restrict__ w,
    const float* __restrict__ alpha,
    const float* __restrict__ hebb)
{
    const int j  = blockIdx.x * (MV_THREADS * 4) + threadIdx.x * 4;
    const int r0 = blockIdx.y * ROWS_PER;

    const float4* __restrict__ wp = reinterpret_cast<const float4*>(w     + (size_t)r0 * N + j);
    const float4* __restrict__ ap = reinterpret_cast<const float4*>(alpha + (size_t)r0 * N + j);
    const float4* __restrict__ hp = reinterpret_cast<const float4*>(hebb  + (size_t)r0 * N + j);
    const int stride4 = N / 4;

    float4 acc = make_float4(0.f, 0.f, 0.f, 0.f);

    #pragma unroll
    for (int i = 0; i < ROWS_PER; ++i) {
        const float  y  = __ldg(&yin[r0 + i]);
        const float4 w4 = __ldcs(wp + (size_t)i * stride4);
        const float4 a4 = __ldcs(ap + (size_t)i * stride4);
        const float4 h4 = __ldg (hp + (size_t)i * stride4);
        acc.x = fmaf(y, fmaf(a4.x, h4.x, w4.x), acc.x);
        acc.y = fmaf(y, fmaf(a4.y, h4.y, w4.y), acc.y);
        acc.z = fmaf(y, fmaf(a4.z, h4.z, w4.z), acc.z);
        acc.w = fmaf(y, fmaf(a4.w, h4.w, w4.w), acc.w);
    }

    *reinterpret_cast<float4*>(&g_partial[(size_t)blockIdx.y * N + j]) = acc;
}

// ---------------------------------------------------------------------------
// Kernel 2a: reduce 1024 partials -> 32 per column. grid (16, 32) = 512 CTAs,
// 32 coalesced strided loads per thread, unrolled for MLP.
// ---------------------------------------------------------------------------
__global__ void __launch_bounds__(256) k_reduce_stage1()
{
    const int j = blockIdx.x * 256 + threadIdx.x;   // column
    const int c = blockIdx.y;                        // chunk
    const float* __restrict__ gp = g_partial + (size_t)c * P_PER_CHUNK * N + j;

    float s = 0.f;
    #pragma unroll
    for (int p = 0; p < P_PER_CHUNK; ++p)
        s += gp[(size_t)p * N];

    g_partial2[(size_t)c * N + j] = s;
}

// ---------------------------------------------------------------------------
// Kernel 2b: final 32-way sum + input + tanh -> yout (d_out[0:N]).
// 512 KB input, fully L2-resident.
// ---------------------------------------------------------------------------
__global__ void __launch_bounds__(256) k_reduce_tanh(
    const float* __restrict__ input,
    float* __restrict__ out_yout)
{
    const int j = blockIdx.x * 256 + threadIdx.x;
    float s = 0.f;
    #pragma unroll
    for (int c = 0; c < CHUNKS; ++c)
        s += g_partial2[(size_t)c * N + j];
    out_yout[j] = tanhf(s + input[j]);
}

// ---------------------------------------------------------------------------
// Kernel 3: flat hebb update (unchanged — measured 19.0us).
// ---------------------------------------------------------------------------
__global__ void __launch_bounds__(256) k_hebb_update(
    const float* __restrict__ hebb,
    const float* __restrict__ yin,
    const float* __restrict__ yout,   // = d_out
    const float* __restrict__ eta,
    float* __restrict__ out_hebb)     // = d_out + N
{
    const size_t t   = (size_t)blockIdx.x * blockDim.x + threadIdx.x;
    const size_t idx = t * 4;                 // element index in N*N
    const int i = (int)(idx >> 12);           // row (N = 2^12)
    const int j = (int)(idx & (N - 1));       // col

    const float e   = eta[0];
    const float ome = 1.f - e;
    const float yie = yin[i] * e;             // warp-uniform broadcast

    const float4 h  = __ldg(reinterpret_cast<const float4*>(hebb + idx));
    const float4 yo = __ldg(reinterpret_cast<const float4*>(yout + j));

    float4 r;
    r.x = fmaf(ome, h.x, yie * yo.x);
    r.y = fmaf(ome, h.y, yie * yo.y);
    r.z = fmaf(ome, h.z, yie * yo.z);
    r.w = fmaf(ome, h.w, yie * yo.w);

    __stcs(reinterpret_cast<float4*>(out_hebb + idx), r);
}

extern "C" void kernel_launch(void* const* d_in, const int* in_sizes, int n_in,
                              void* d_out, int out_size)
{
    const float* input = (const float*)d_in[0];
    const float* yin   = (const float*)d_in[1];
    const float* hebb  = (const float*)d_in[2];
    const float* w     = (const float*)d_in[3];
    const float* alpha = (const float*)d_in[4];
    const float* eta   = (const float*)d_in[5];

    float* out      = (float*)d_out;
    float* out_yout = out;
    float* out_hebb = out + N;

    dim3 g1(COL_BLOCKS, SPLITS);   // 4 x 1024 = 4096 CTAs
    k_matvec_partial<<<g1, MV_THREADS>>>(yin, w, alpha, hebb);

    dim3 g2a(N / 256, CHUNKS);     // 16 x 32 = 512 CTAs
    k_reduce_stage1<<<g2a, 256>>>();

    k_reduce_tanh<<<N / 256, 256>>>(input, out_yout);

    const int hb_blocks = (N * N) / (4 * 256);   // 16384
    k_hebb_update<<<hb_blocks, 256>>>(hebb, yin, out_yout, eta, out_hebb);
}

// round 15
// speedup vs baseline: 1.0689x; 1.0347x over previous
#include <cuda_runtime.h>
#include <math.h>

// Two launches:
//   kA (persistent): phase 1 = split-K matvec partials (2048 tiles over 512
//       co-resident CTAs, identical per-tile body to the measured 33.7us k1)
//       -> grid barrier -> phase 2 = column reduction + tanh -> yout.
//   kB: flat hebb update, 16384 CTAs, 1 float4/thread (measured 19.2us,
//       byte-identical).

#define N 4096
#define SPLITS 512             // row splits (split-K)
#define ROWS_PER (N / SPLITS)  // 8 rows per split
#define PK_CTAS 512            // persistent CTAs (co-resident: 4/SM * 148 = 592)
#define PK_THREADS 256
#define TILES_PER_CTA 4        // 512 CTAs * 4 = 2048 tiles = 4 colblocks * 512 splits

// Deterministic split-K scratch (8 MB). No atomics on data -> bit-identical.
__device__ float g_partial[SPLITS * N];

// Grid-barrier state. count self-resets to 0 each launch (replay-safe);
// gen increments monotonically (equality test tolerates wraparound).
__device__ unsigned int g_bar_count = 0;
__device__ unsigned int g_bar_gen = 0;

// ---------------------------------------------------------------------------
// Kernel A: persistent matvec + reduction.
// ---------------------------------------------------------------------------
__global__ void __launch_bounds__(PK_THREADS, 4) k_matvec_reduce(
    const float* __restrict__ input,
    const float* __restrict__ yin,
    const float* __restrict__ w,
    const float* __restrict__ alpha,
    const float* __restrict__ hebb,
    float* __restrict__ out_yout)
{
    const int tid = threadIdx.x;
    const int b   = blockIdx.x;

    // ---------------- Phase 1: 4 matvec tiles ----------------
    // Column block is fixed per CTA (b & 3); split advances by 128 per tile.
    const int j = (b & 3) * (PK_THREADS * 4) + tid * 4;   // this thread's 4 cols
    const int stride4 = N / 4;

    #pragma unroll
    for (int t = 0; t < TILES_PER_CTA; ++t) {
        const int sp = (b >> 2) + t * (PK_CTAS / 4);      // split 0..511
        const int r0 = sp * ROWS_PER;

        const float4* __restrict__ wp = reinterpret_cast<const float4*>(w     + (size_t)r0 * N + j);
        const float4* __restrict__ ap = reinterpret_cast<const float4*>(alpha + (size_t)r0 * N + j);
        const float4* __restrict__ hp = reinterpret_cast<const float4*>(hebb  + (size_t)r0 * N + j);

        float4 acc = make_float4(0.f, 0.f, 0.f, 0.f);

        #pragma unroll
        for (int i = 0; i < ROWS_PER; ++i) {
            const float  y  = __ldg(&yin[r0 + i]);
            const float4 w4 = __ldcs(wp + (size_t)i * stride4);
            const float4 a4 = __ldcs(ap + (size_t)i * stride4);
            const float4 h4 = __ldg (hp + (size_t)i * stride4);
            acc.x = fmaf(y, fmaf(a4.x, h4.x, w4.x), acc.x);
            acc.y = fmaf(y, fmaf(a4.y, h4.y, w4.y), acc.y);
            acc.z = fmaf(y, fmaf(a4.z, h4.z, w4.z), acc.z);
            acc.w = fmaf(y, fmaf(a4.w, h4.w, w4.w), acc.w);
        }

        *reinterpret_cast<float4*>(&g_partial[(size_t)sp * N + j]) = acc;
    }

    // ---------------- Grid barrier ----------------
    __syncthreads();
    if (tid == 0) {
        __threadfence();                                   // publish partials
        const unsigned int gen = atomicAdd(&g_bar_gen, 0); // read gen first
        if (atomicAdd(&g_bar_count, 1) == (unsigned)(gridDim.x - 1)) {
            g_bar_count = 0;                               // reset for next replay
            atomicAdd(&g_bar_gen, 1);                      // release
        } else {
            while (atomicAdd(&g_bar_gen, 0) == gen) __nanosleep(32);
        }
        __threadfence();                                   // acquire
    }
    __syncthreads();

    // ---------------- Phase 2: reduction + tanh (CTAs 0..127) ----------------
    if (b < 128) {
        __shared__ float red[8][32];
        const int sg  = tid >> 5;                  // 0..7 split-group
        const int c   = tid & 31;                  // 0..31 col within CTA
        const int col = b * 32 + c;                // global column

        const float* __restrict__ gp = g_partial + (size_t)sg * (SPLITS / 8) * N + col;
        float s = 0.f;
        #pragma unroll 16
        for (int p = 0; p < SPLITS / 8; ++p)       // 64 partials, coalesced
            s += gp[(size_t)p * N];

        red[sg][c] = s;
        __syncthreads();

        if (sg == 0) {
            float tsum = red[0][c];
            #pragma unroll
            for (int g = 1; g < 8; ++g)
                tsum += red[g][c];
            out_yout[col] = tanhf(tsum + __ldg(&input[col]));
        }
    }
}

// ---------------------------------------------------------------------------
// Kernel B: flat hebb update (byte-identical to measured 19.2us version).
// ---------------------------------------------------------------------------
__global__ void __launch_bounds__(256) k_hebb_update(
    const float* __restrict__ hebb,
    const float* __restrict__ yin,
    const float* __restrict__ yout,   // = d_out
    const float* __restrict__ eta,
    float* __restrict__ out_hebb)     // = d_out + N
{
    const size_t t   = (size_t)blockIdx.x * blockDim.x + threadIdx.x;
    const size_t idx = t * 4;                 // element index in N*N
    const int i = (int)(idx >> 12);           // row (N = 2^12)
    const int j = (int)(idx & (N - 1));       // col

    const float e   = eta[0];
    const float ome = 1.f - e;
    const float yie = yin[i] * e;             // warp-uniform broadcast

    const float4 h  = __ldg(reinterpret_cast<const float4*>(hebb + idx));
    const float4 yo = __ldg(reinterpret_cast<const float4*>(yout + j));

    float4 r;
    r.x = fmaf(ome, h.x, yie * yo.x);
    r.y = fmaf(ome, h.y, yie * yo.y);
    r.z = fmaf(ome, h.z, yie * yo.z);
    r.w = fmaf(ome, h.w, yie * yo.w);

    __stcs(reinterpret_cast<float4*>(out_hebb + idx), r);
}

extern "C" void kernel_launch(void* const* d_in, const int* in_sizes, int n_in,
                              void* d_out, int out_size)
{
    const float* input = (const float*)d_in[0];
    const float* yin   = (const float*)d_in[1];
    const float* hebb  = (const float*)d_in[2];
    const float* w     = (const float*)d_in[3];
    const float* alpha = (const float*)d_in[4];
    const float* eta   = (const float*)d_in[5];

    float* out      = (float*)d_out;
    float* out_yout = out;
    float* out_hebb = out + N;

    k_matvec_reduce<<<PK_CTAS, PK_THREADS>>>(input, yin, w, alpha, hebb, out_yout);

    const int hb_blocks = (N * N) / (4 * 256);   // 16384
    k_hebb_update<<<hb_blocks, 256>>>(hebb, yin, out_yout, eta, out_hebb);
}